// round 2
// baseline (speedup 1.0000x reference)
#include <cuda_runtime.h>
#include <math.h>

// ---------------- problem constants ----------------
#define DIM    768
#define PE     200
#define KIN    1536           // 2*DIM, concat of left/right span endpoints
#define SPANL  20             // MAX_SPAN_LEN
#define NPAIR  256            // 8 batches * 32 pairs
#define ROWS   5120           // NPAIR * SPANL
#define EMB    128
#define VOCAB  30522
#define SEQ    512

// ---------------- scratch (device globals; no allocations allowed) ----------------
__device__ __align__(16) float gX [NPAIR * KIN];   // gathered [lh|rh] per pair
__device__ __align__(16) float gA [NPAIR * DIM];   // pair part of pre-activation (incl b1)
__device__ __align__(16) float gP [SPANL * DIM];   // positional part of pre-activation
__device__ __align__(16) float gH1[ROWS * DIM];
__device__ __align__(16) float gT [ROWS * DIM];
__device__ __align__(16) float gH2[ROWS * DIM];
__device__ __align__(16) float gH3[ROWS * EMB];

__device__ __forceinline__ float gelu_exact(float x) {
    return 0.5f * x * (1.0f + erff(x * 0.70710678118654752440f));
}

// ---------------- 1) gather span endpoints into gX [NPAIR, KIN] ----------------
__global__ void gather_kernel(const float* __restrict__ hs, const int* __restrict__ pairs) {
    int idx = blockIdx.x * 256 + threadIdx.x;
    if (idx >= NPAIR * KIN) return;
    int p = idx / KIN;
    int k = idx - p * KIN;
    int b = p >> 5;                              // p = b*32 + pp
    int tok, kk;
    if (k < DIM) { tok = pairs[2 * p];     kk = k; }
    else         { tok = pairs[2 * p + 1]; kk = k - DIM; }
    gX[idx] = hs[((size_t)(b * SEQ + tok)) * DIM + kk];
}

// ---------------- 2) positional projection: gP[l, :] = pos_emb[l] @ W1[1536:1736, :] ----------------
__global__ void pos_proj_kernel(const float* __restrict__ pe, const float* __restrict__ W1) {
    __shared__ float sp[PE];
    int l = blockIdx.y;
    int c = blockIdx.x * 256 + threadIdx.x;      // 0..767
    if (threadIdx.x < PE) sp[threadIdx.x] = pe[l * PE + threadIdx.x];
    __syncthreads();
    float acc = 0.0f;
    #pragma unroll 4
    for (int k = 0; k < PE; k++)
        acc += sp[k] * W1[(size_t)(KIN + k) * DIM + c];
    gP[l * DIM + c] = acc;
}

// ---------------- generic fp32 SGEMM:  C[M,N] = A[M,K] @ B[K,N] (+bias) ----------------
// BM=BN=64, BK=16, 256 threads, 4x4 microtile. Requires M%64==0, N%64==0, K%16==0.
__global__ void sgemm_bias(const float* __restrict__ A, const float* __restrict__ B,
                           const float* __restrict__ bias, float* __restrict__ C,
                           int M, int N, int K) {
    __shared__ float As[16][68];
    __shared__ float Bs[16][68];
    int tid = threadIdx.x;
    int tx = tid & 15, ty = tid >> 4;
    int m0 = blockIdx.y * 64, n0 = blockIdx.x * 64;

    int ar = tid >> 2, aq = tid & 3;             // A tile: 64 rows x 16 k
    int bk = tid >> 4, bq = tid & 15;            // B tile: 16 k  x 64 n

    float acc[4][4];
    #pragma unroll
    for (int i = 0; i < 4; i++)
        #pragma unroll
        for (int j = 0; j < 4; j++) acc[i][j] = 0.0f;

    for (int k0 = 0; k0 < K; k0 += 16) {
        float4 av = *(const float4*)&A[(size_t)(m0 + ar) * K + k0 + aq * 4];
        float4 bv = *(const float4*)&B[(size_t)(k0 + bk) * N + n0 + bq * 4];
        As[aq * 4 + 0][ar] = av.x;
        As[aq * 4 + 1][ar] = av.y;
        As[aq * 4 + 2][ar] = av.z;
        As[aq * 4 + 3][ar] = av.w;
        *(float4*)&Bs[bk][bq * 4] = bv;
        __syncthreads();
        #pragma unroll
        for (int k = 0; k < 16; k++) {
            float4 a = *(const float4*)&As[k][ty * 4];
            float4 b = *(const float4*)&Bs[k][tx * 4];
            float ai[4] = {a.x, a.y, a.z, a.w};
            float bj[4] = {b.x, b.y, b.z, b.w};
            #pragma unroll
            for (int i = 0; i < 4; i++)
                #pragma unroll
                for (int j = 0; j < 4; j++) acc[i][j] += ai[i] * bj[j];
        }
        __syncthreads();
    }

    float bb[4] = {0.f, 0.f, 0.f, 0.f};
    if (bias) {
        #pragma unroll
        for (int j = 0; j < 4; j++) bb[j] = bias[n0 + tx * 4 + j];
    }
    #pragma unroll
    for (int i = 0; i < 4; i++) {
        int row = m0 + ty * 4 + i;
        #pragma unroll
        for (int j = 0; j < 4; j++)
            C[(size_t)row * N + n0 + tx * 4 + j] = acc[i][j] + bb[j];
    }
}

// ---------------- decoder SGEMM:  C[M,N] = A[M,K] @ B[N,K]^T   (B = Wdec, K contiguous) ----------------
// N not divisible by 64 -> guarded. K=128.
__global__ void sgemm_bt(const float* __restrict__ A, const float* __restrict__ B,
                         float* __restrict__ C, int M, int N, int K) {
    __shared__ float As[16][68];
    __shared__ float Bs[16][68];
    int tid = threadIdx.x;
    int tx = tid & 15, ty = tid >> 4;
    int m0 = blockIdx.y * 64, n0 = blockIdx.x * 64;

    int ar = tid >> 2, aq = tid & 3;             // A tile: 64 rows x 16 k
    int br = tid >> 2, q2 = tid & 3;             // B tile: 64 n-rows x 16 k

    float acc[4][4];
    #pragma unroll
    for (int i = 0; i < 4; i++)
        #pragma unroll
        for (int j = 0; j < 4; j++) acc[i][j] = 0.0f;

    for (int k0 = 0; k0 < K; k0 += 16) {
        float4 av = *(const float4*)&A[(size_t)(m0 + ar) * K + k0 + aq * 4];
        int n = n0 + br;
        float4 bv = make_float4(0.f, 0.f, 0.f, 0.f);
        if (n < N) bv = *(const float4*)&B[(size_t)n * K + k0 + q2 * 4];
        As[aq * 4 + 0][ar] = av.x;
        As[aq * 4 + 1][ar] = av.y;
        As[aq * 4 + 2][ar] = av.z;
        As[aq * 4 + 3][ar] = av.w;
        Bs[q2 * 4 + 0][br] = bv.x;
        Bs[q2 * 4 + 1][br] = bv.y;
        Bs[q2 * 4 + 2][br] = bv.z;
        Bs[q2 * 4 + 3][br] = bv.w;
        __syncthreads();
        #pragma unroll
        for (int k = 0; k < 16; k++) {
            float4 a = *(const float4*)&As[k][ty * 4];
            float4 b = *(const float4*)&Bs[k][tx * 4];
            float ai[4] = {a.x, a.y, a.z, a.w};
            float bj[4] = {b.x, b.y, b.z, b.w};
            #pragma unroll
            for (int i = 0; i < 4; i++)
                #pragma unroll
                for (int j = 0; j < 4; j++) acc[i][j] += ai[i] * bj[j];
        }
        __syncthreads();
    }

    #pragma unroll
    for (int i = 0; i < 4; i++) {
        int row = m0 + ty * 4 + i;
        #pragma unroll
        for (int j = 0; j < 4; j++) {
            int col = n0 + tx * 4 + j;
            if (col < N) C[(size_t)row * N + col] = acc[i][j];
        }
    }
}

// ---------------- fused (add) + exact-GELU + LayerNorm, row-wise over 768 ----------------
// addMode=1: x = gA[row/20] + gP[row%20]; addMode=0: x = inA[row]
__global__ void gelu_ln_kernel(const float* __restrict__ inA, const float* __restrict__ inP,
                               const float* __restrict__ gamma, const float* __restrict__ beta,
                               float* __restrict__ out, int addMode) {
    int row = blockIdx.x;
    int tid = threadIdx.x;                       // 256 threads, 3 elems each
    float v[3];
    if (addMode) {
        const float* ra = inA + (size_t)(row / SPANL) * DIM;
        const float* rp = inP + (size_t)(row % SPANL) * DIM;
        #pragma unroll
        for (int c = 0; c < 3; c++) {
            int j = tid + c * 256;
            v[c] = gelu_exact(ra[j] + rp[j]);
        }
    } else {
        const float* ra = inA + (size_t)row * DIM;
        #pragma unroll
        for (int c = 0; c < 3; c++) {
            int j = tid + c * 256;
            v[c] = gelu_exact(ra[j]);
        }
    }
    float s  = v[0] + v[1] + v[2];
    float s2 = v[0] * v[0] + v[1] * v[1] + v[2] * v[2];
    #pragma unroll
    for (int o = 16; o > 0; o >>= 1) {
        s  += __shfl_xor_sync(0xffffffffu, s,  o);
        s2 += __shfl_xor_sync(0xffffffffu, s2, o);
    }
    __shared__ float rs[8], rs2[8];
    __shared__ float tmu, tinv;
    int wid = tid >> 5, lane = tid & 31;
    if (lane == 0) { rs[wid] = s; rs2[wid] = s2; }
    __syncthreads();
    if (tid == 0) {
        float a = 0.f, b = 0.f;
        #pragma unroll
        for (int i = 0; i < 8; i++) { a += rs[i]; b += rs2[i]; }
        float mu  = a * (1.0f / 768.0f);
        float var = b * (1.0f / 768.0f) - mu * mu;
        tmu = mu;
        tinv = rsqrtf(var + 1e-12f);
    }
    __syncthreads();
    float mu = tmu, inv = tinv;
    #pragma unroll
    for (int c = 0; c < 3; c++) {
        int j = tid + c * 256;
        out[(size_t)row * DIM + j] = (v[c] - mu) * inv * gamma[j] + beta[j];
    }
}

// ---------------- launcher ----------------
extern "C" void kernel_launch(void* const* d_in, const int* in_sizes, int n_in,
                              void* d_out, int out_size) {
    (void)in_sizes; (void)n_in; (void)out_size;
    const float* hs    = (const float*)d_in[0];
    const int*   pairs = (const int*)  d_in[1];
    const float* pos   = (const float*)d_in[2];
    const float* W1    = (const float*)d_in[3];
    const float* b1    = (const float*)d_in[4];
    const float* g1    = (const float*)d_in[5];
    const float* be1   = (const float*)d_in[6];
    const float* W2    = (const float*)d_in[7];
    const float* b2    = (const float*)d_in[8];
    const float* g2    = (const float*)d_in[9];
    const float* be2   = (const float*)d_in[10];
    const float* Wp    = (const float*)d_in[11];
    const float* bp    = (const float*)d_in[12];
    const float* Wdec  = (const float*)d_in[13];
    float* out = (float*)d_out;

    float *pX, *pA, *pP, *pH1, *pT, *pH2, *pH3;
    cudaGetSymbolAddress((void**)&pX,  gX);
    cudaGetSymbolAddress((void**)&pA,  gA);
    cudaGetSymbolAddress((void**)&pP,  gP);
    cudaGetSymbolAddress((void**)&pH1, gH1);
    cudaGetSymbolAddress((void**)&pT,  gT);
    cudaGetSymbolAddress((void**)&pH2, gH2);
    cudaGetSymbolAddress((void**)&pH3, gH3);

    // 1) gather endpoints
    gather_kernel<<<(NPAIR * KIN + 255) / 256, 256>>>(hs, pairs);
    // 2) pair projection: gA = [lh|rh] @ W1[0:1536] + b1   (256 x 768, K=1536)
    sgemm_bias<<<dim3(DIM / 64, NPAIR / 64), 256>>>(pX, W1, b1, pA, NPAIR, DIM, KIN);
    // 3) positional projection: gP = pos_emb @ W1[1536:1736]   (20 x 768, K=200)
    pos_proj_kernel<<<dim3(3, SPANL), 256>>>(pos, W1);
    // 4) h1 = LN(gelu(gA[pair] + gP[l]))
    gelu_ln_kernel<<<ROWS, 256>>>(pA, pP, g1, be1, pH1, 1);
    // 5) gT = h1 @ W2 + b2   (5120 x 768, K=768)
    sgemm_bias<<<dim3(DIM / 64, ROWS / 64), 256>>>(pH1, W2, b2, pT, ROWS, DIM, DIM);
    // 6) h2 = LN(gelu(gT))
    gelu_ln_kernel<<<ROWS, 256>>>(pT, nullptr, g2, be2, pH2, 0);
    // 7) h3 = h2 @ Wp + bp   (5120 x 128, K=768)
    sgemm_bias<<<dim3(EMB / 64, ROWS / 64), 256>>>(pH2, Wp, bp, pH3, ROWS, EMB, DIM);
    // 8) out = h3 @ Wdec^T   (5120 x 30522, K=128)
    sgemm_bt<<<dim3((VOCAB + 63) / 64, ROWS / 64), 256>>>(pH3, Wdec, out, ROWS, VOCAB, EMB);
}

// round 4
// speedup vs baseline: 1.1472x; 1.1472x over previous
#include <cuda_runtime.h>
#include <cuda_bf16.h>
#include <math.h>

// ---------------- problem constants ----------------
#define DIM    768
#define PE     200
#define KIN    1536           // 2*DIM
#define SPANL  20
#define NPAIR  256
#define ROWS   5120
#define EMB    128
#define VOCAB  30522
#define SEQ    512

// ---------------- scratch ----------------
__device__ __align__(16) float gX [NPAIR * KIN];
__device__ __align__(16) float gA [NPAIR * DIM];
__device__ __align__(16) float gP [SPANL * DIM];
__device__ __align__(16) float gH1[ROWS * DIM];
__device__ __align__(16) float gT [ROWS * DIM];
__device__ __align__(16) float gH2[ROWS * DIM];
__device__ __align__(16) float gH3[ROWS * EMB];
// bf16 hi/lo splits for tensor-core decoder
__device__ __align__(16) __nv_bfloat16 gH3h[ROWS * EMB];
__device__ __align__(16) __nv_bfloat16 gH3l[ROWS * EMB];
__device__ __align__(16) __nv_bfloat16 gWh [VOCAB * EMB];
__device__ __align__(16) __nv_bfloat16 gWl [VOCAB * EMB];

__device__ __forceinline__ float gelu_exact(float x) {
    return 0.5f * x * (1.0f + erff(x * 0.70710678118654752440f));
}

// ---------------- 1) gather span endpoints ----------------
__global__ void gather_kernel(const float* __restrict__ hs, const int* __restrict__ pairs) {
    int idx = blockIdx.x * 256 + threadIdx.x;
    if (idx >= NPAIR * KIN) return;
    int p = idx / KIN;
    int k = idx - p * KIN;
    int b = p >> 5;
    int tok, kk;
    if (k < DIM) { tok = pairs[2 * p];     kk = k; }
    else         { tok = pairs[2 * p + 1]; kk = k - DIM; }
    gX[idx] = hs[((size_t)(b * SEQ + tok)) * DIM + kk];
}

// ---------------- 2) positional projection ----------------
__global__ void pos_proj_kernel(const float* __restrict__ pe, const float* __restrict__ W1) {
    __shared__ float sp[PE];
    int l = blockIdx.y;
    int c = blockIdx.x * 256 + threadIdx.x;
    if (threadIdx.x < PE) sp[threadIdx.x] = pe[l * PE + threadIdx.x];
    __syncthreads();
    float acc = 0.0f;
    #pragma unroll 4
    for (int k = 0; k < PE; k++)
        acc += sp[k] * W1[(size_t)(KIN + k) * DIM + c];
    gP[l * DIM + c] = acc;
}

// ---------------- fp32 SGEMM (used for small/medium stages) ----------------
__global__ void sgemm_bias(const float* __restrict__ A, const float* __restrict__ B,
                           const float* __restrict__ bias, float* __restrict__ C,
                           int M, int N, int K) {
    __shared__ float As[16][68];
    __shared__ float Bs[16][68];
    int tid = threadIdx.x;
    int tx = tid & 15, ty = tid >> 4;
    int m0 = blockIdx.y * 64, n0 = blockIdx.x * 64;
    int ar = tid >> 2, aq = tid & 3;
    int bk = tid >> 4, bq = tid & 15;

    float acc[4][4];
    #pragma unroll
    for (int i = 0; i < 4; i++)
        #pragma unroll
        for (int j = 0; j < 4; j++) acc[i][j] = 0.0f;

    for (int k0 = 0; k0 < K; k0 += 16) {
        float4 av = *(const float4*)&A[(size_t)(m0 + ar) * K + k0 + aq * 4];
        float4 bv = *(const float4*)&B[(size_t)(k0 + bk) * N + n0 + bq * 4];
        As[aq * 4 + 0][ar] = av.x;
        As[aq * 4 + 1][ar] = av.y;
        As[aq * 4 + 2][ar] = av.z;
        As[aq * 4 + 3][ar] = av.w;
        *(float4*)&Bs[bk][bq * 4] = bv;
        __syncthreads();
        #pragma unroll
        for (int k = 0; k < 16; k++) {
            float4 a = *(const float4*)&As[k][ty * 4];
            float4 b = *(const float4*)&Bs[k][tx * 4];
            float ai[4] = {a.x, a.y, a.z, a.w};
            float bj[4] = {b.x, b.y, b.z, b.w};
            #pragma unroll
            for (int i = 0; i < 4; i++)
                #pragma unroll
                for (int j = 0; j < 4; j++) acc[i][j] += ai[i] * bj[j];
        }
        __syncthreads();
    }

    float bb[4] = {0.f, 0.f, 0.f, 0.f};
    if (bias) {
        #pragma unroll
        for (int j = 0; j < 4; j++) bb[j] = bias[n0 + tx * 4 + j];
    }
    #pragma unroll
    for (int i = 0; i < 4; i++) {
        int row = m0 + ty * 4 + i;
        #pragma unroll
        for (int j = 0; j < 4; j++)
            C[(size_t)row * N + n0 + tx * 4 + j] = acc[i][j] + bb[j];
    }
}

// ---------------- fused GELU + LayerNorm ----------------
__global__ void gelu_ln_kernel(const float* __restrict__ inA, const float* __restrict__ inP,
                               const float* __restrict__ gamma, const float* __restrict__ beta,
                               float* __restrict__ out, int addMode) {
    int row = blockIdx.x;
    int tid = threadIdx.x;
    float v[3];
    if (addMode) {
        const float* ra = inA + (size_t)(row / SPANL) * DIM;
        const float* rp = inP + (size_t)(row % SPANL) * DIM;
        #pragma unroll
        for (int c = 0; c < 3; c++) {
            int j = tid + c * 256;
            v[c] = gelu_exact(ra[j] + rp[j]);
        }
    } else {
        const float* ra = inA + (size_t)row * DIM;
        #pragma unroll
        for (int c = 0; c < 3; c++) {
            int j = tid + c * 256;
            v[c] = gelu_exact(ra[j]);
        }
    }
    float s  = v[0] + v[1] + v[2];
    float s2 = v[0] * v[0] + v[1] * v[1] + v[2] * v[2];
    #pragma unroll
    for (int o = 16; o > 0; o >>= 1) {
        s  += __shfl_xor_sync(0xffffffffu, s,  o);
        s2 += __shfl_xor_sync(0xffffffffu, s2, o);
    }
    __shared__ float rs[8], rs2[8];
    __shared__ float tmu, tinv;
    int wid = tid >> 5, lane = tid & 31;
    if (lane == 0) { rs[wid] = s; rs2[wid] = s2; }
    __syncthreads();
    if (tid == 0) {
        float a = 0.f, b = 0.f;
        #pragma unroll
        for (int i = 0; i < 8; i++) { a += rs[i]; b += rs2[i]; }
        float mu  = a * (1.0f / 768.0f);
        float var = b * (1.0f / 768.0f) - mu * mu;
        tmu = mu;
        tinv = rsqrtf(var + 1e-12f);
    }
    __syncthreads();
    float mu = tmu, inv = tinv;
    #pragma unroll
    for (int c = 0; c < 3; c++) {
        int j = tid + c * 256;
        out[(size_t)row * DIM + j] = (v[c] - mu) * inv * gamma[j] + beta[j];
    }
}

// ---------------- bf16 hi/lo split ----------------
__global__ void split_kernel(const float* __restrict__ src,
                             __nv_bfloat16* __restrict__ hi,
                             __nv_bfloat16* __restrict__ lo, int n) {
    int i = blockIdx.x * 256 + threadIdx.x;
    if (i >= n) return;
    float a = src[i];
    __nv_bfloat16 h = __float2bfloat16(a);
    float r = a - __bfloat162float(h);
    hi[i] = h;
    lo[i] = __float2bfloat16(r);
}

// ---------------- decoder: C[5120, 30522] = A[5120,128] @ W[30522,128]^T ----------------
// bf16 split tensor-core GEMM: C ~= Ah Bh^T + Ah Bl^T + Al Bh^T
// CTA tile 128x128, 8 warps (4x2), warp tile 32x64, mma m16n8k16.
#define SROW 24   // smem row stride in bf16 (16 data + 8 pad; 48B, 16B-aligned)

__device__ __forceinline__ void mma_bf16(float* c, const unsigned* a, unsigned b0, unsigned b1) {
    asm volatile(
        "mma.sync.aligned.m16n8k16.row.col.f32.bf16.bf16.f32 "
        "{%0,%1,%2,%3}, {%4,%5,%6,%7}, {%8,%9}, {%0,%1,%2,%3};\n"
        : "+f"(c[0]), "+f"(c[1]), "+f"(c[2]), "+f"(c[3])
        : "r"(a[0]), "r"(a[1]), "r"(a[2]), "r"(a[3]), "r"(b0), "r"(b1));
}

__global__ __launch_bounds__(256, 2)
void decoder_mma_kernel(const __nv_bfloat16* __restrict__ Ah,
                        const __nv_bfloat16* __restrict__ Al,
                        const __nv_bfloat16* __restrict__ Bh,
                        const __nv_bfloat16* __restrict__ Bl,
                        float* __restrict__ C) {
    __shared__ __nv_bfloat16 sAh[128 * SROW];
    __shared__ __nv_bfloat16 sAl[128 * SROW];
    __shared__ __nv_bfloat16 sBh[128 * SROW];
    __shared__ __nv_bfloat16 sBl[128 * SROW];

    int tid  = threadIdx.x;
    int warp = tid >> 5, lane = tid & 31;
    int wm = warp >> 1, wn = warp & 1;       // 4 x 2 warp grid
    int grp = lane >> 2, quad = lane & 3;
    int m0 = blockIdx.y * 128, n0 = blockIdx.x * 128;

    int lrow = tid >> 1, lpart = tid & 1;    // global-load mapping: 2 thr/row, 8 bf16 each

    float acc[2][8][4];
    #pragma unroll
    for (int i = 0; i < 2; i++)
        #pragma unroll
        for (int j = 0; j < 8; j++)
            #pragma unroll
            for (int q = 0; q < 4; q++) acc[i][j][q] = 0.0f;

    for (int k0 = 0; k0 < EMB; k0 += 16) {
        // stage A (rows always valid: 5120 % 128 == 0)
        size_t aoff = (size_t)(m0 + lrow) * EMB + k0 + lpart * 8;
        *(uint4*)&sAh[lrow * SROW + lpart * 8] = *(const uint4*)&Ah[aoff];
        *(uint4*)&sAl[lrow * SROW + lpart * 8] = *(const uint4*)&Al[aoff];
        // stage B (vocab rows guarded)
        int nrow = n0 + lrow;
        uint4 bh = make_uint4(0u, 0u, 0u, 0u), bl = bh;
        if (nrow < VOCAB) {
            size_t boff = (size_t)nrow * EMB + k0 + lpart * 8;
            bh = *(const uint4*)&Bh[boff];
            bl = *(const uint4*)&Bl[boff];
        }
        *(uint4*)&sBh[lrow * SROW + lpart * 8] = bh;
        *(uint4*)&sBl[lrow * SROW + lpart * 8] = bl;
        __syncthreads();

        // A fragments for both m-tiles, both splits
        unsigned a_h[2][4], a_l[2][4];
        #pragma unroll
        for (int mt = 0; mt < 2; mt++) {
            int r = wm * 32 + mt * 16;
            a_h[mt][0] = *(const unsigned*)&sAh[(r + grp    ) * SROW + quad * 2    ];
            a_h[mt][1] = *(const unsigned*)&sAh[(r + grp + 8) * SROW + quad * 2    ];
            a_h[mt][2] = *(const unsigned*)&sAh[(r + grp    ) * SROW + quad * 2 + 8];
            a_h[mt][3] = *(const unsigned*)&sAh[(r + grp + 8) * SROW + quad * 2 + 8];
            a_l[mt][0] = *(const unsigned*)&sAl[(r + grp    ) * SROW + quad * 2    ];
            a_l[mt][1] = *(const unsigned*)&sAl[(r + grp + 8) * SROW + quad * 2    ];
            a_l[mt][2] = *(const unsigned*)&sAl[(r + grp    ) * SROW + quad * 2 + 8];
            a_l[mt][3] = *(const unsigned*)&sAl[(r + grp + 8) * SROW + quad * 2 + 8];
        }

        #pragma unroll
        for (int nt = 0; nt < 8; nt++) {
            int c = wn * 64 + nt * 8 + grp;
            unsigned bh0 = *(const unsigned*)&sBh[c * SROW + quad * 2    ];
            unsigned bh1 = *(const unsigned*)&sBh[c * SROW + quad * 2 + 8];
            unsigned bl0 = *(const unsigned*)&sBl[c * SROW + quad * 2    ];
            unsigned bl1 = *(const unsigned*)&sBl[c * SROW + quad * 2 + 8];
            #pragma unroll
            for (int mt = 0; mt < 2; mt++) {
                mma_bf16(acc[mt][nt], a_h[mt], bh0, bh1);
                mma_bf16(acc[mt][nt], a_h[mt], bl0, bl1);
                mma_bf16(acc[mt][nt], a_l[mt], bh0, bh1);
            }
        }
        __syncthreads();
    }

    // epilogue: scattered 8B stores (32B sectors stay full)
    #pragma unroll
    for (int mt = 0; mt < 2; mt++) {
        #pragma unroll
        for (int nt = 0; nt < 8; nt++) {
            int row = m0 + wm * 32 + mt * 16 + grp;
            int col = n0 + wn * 64 + nt * 8 + quad * 2;
            if (col < VOCAB) {   // VOCAB even, col even -> covers col+1 too
                float2* p0 = (float2*)&C[(size_t)row * VOCAB + col];
                *p0 = make_float2(acc[mt][nt][0], acc[mt][nt][1]);
                float2* p1 = (float2*)&C[(size_t)(row + 8) * VOCAB + col];
                *p1 = make_float2(acc[mt][nt][2], acc[mt][nt][3]);
            }
        }
    }
}

// ---------------- launcher ----------------
extern "C" void kernel_launch(void* const* d_in, const int* in_sizes, int n_in,
                              void* d_out, int out_size) {
    (void)in_sizes; (void)n_in; (void)out_size;
    const float* hs    = (const float*)d_in[0];
    const int*   pairs = (const int*)  d_in[1];
    const float* pos   = (const float*)d_in[2];
    const float* W1    = (const float*)d_in[3];
    const float* b1    = (const float*)d_in[4];
    const float* g1    = (const float*)d_in[5];
    const float* be1   = (const float*)d_in[6];
    const float* W2    = (const float*)d_in[7];
    const float* b2    = (const float*)d_in[8];
    const float* g2    = (const float*)d_in[9];
    const float* be2   = (const float*)d_in[10];
    const float* Wp    = (const float*)d_in[11];
    const float* bp    = (const float*)d_in[12];
    const float* Wdec  = (const float*)d_in[13];
    float* out = (float*)d_out;

    float *pX, *pA, *pP, *pH1, *pT, *pH2, *pH3;
    __nv_bfloat16 *pH3h, *pH3l, *pWh, *pWl;
    cudaGetSymbolAddress((void**)&pX,   gX);
    cudaGetSymbolAddress((void**)&pA,   gA);
    cudaGetSymbolAddress((void**)&pP,   gP);
    cudaGetSymbolAddress((void**)&pH1,  gH1);
    cudaGetSymbolAddress((void**)&pT,   gT);
    cudaGetSymbolAddress((void**)&pH2,  gH2);
    cudaGetSymbolAddress((void**)&pH3,  gH3);
    cudaGetSymbolAddress((void**)&pH3h, gH3h);
    cudaGetSymbolAddress((void**)&pH3l, gH3l);
    cudaGetSymbolAddress((void**)&pWh,  gWh);
    cudaGetSymbolAddress((void**)&pWl,  gWl);

    // 1) gather endpoints
    gather_kernel<<<(NPAIR * KIN + 255) / 256, 256>>>(hs, pairs);
    // 2) pair projection (256 x 768, K=1536)
    sgemm_bias<<<dim3(DIM / 64, NPAIR / 64), 256>>>(pX, W1, b1, pA, NPAIR, DIM, KIN);
    // 3) positional projection (20 x 768, K=200)
    pos_proj_kernel<<<dim3(3, SPANL), 256>>>(pos, W1);
    // 4) h1 = LN(gelu(gA[pair] + gP[l]))
    gelu_ln_kernel<<<ROWS, 256>>>(pA, pP, g1, be1, pH1, 1);
    // 5) gT = h1 @ W2 + b2  (5120 x 768, K=768)
    sgemm_bias<<<dim3(DIM / 64, ROWS / 64), 256>>>(pH1, W2, b2, pT, ROWS, DIM, DIM);
    // 6) h2 = LN(gelu(gT))
    gelu_ln_kernel<<<ROWS, 256>>>(pT, nullptr, g2, be2, pH2, 0);
    // 7) h3 = h2 @ Wp + bp  (5120 x 128, K=768)
    sgemm_bias<<<dim3(EMB / 64, ROWS / 64), 256>>>(pH2, Wp, bp, pH3, ROWS, EMB, DIM);
    // 8a) bf16 hi/lo splits (Wdec split could overlap earlier stages; it has no deps)
    split_kernel<<<(VOCAB * EMB + 255) / 256, 256>>>(Wdec, pWh, pWl, VOCAB * EMB);
    split_kernel<<<(ROWS * EMB + 255) / 256, 256>>>(pH3, pH3h, pH3l, ROWS * EMB);
    // 8b) decoder on tensor cores
    decoder_mma_kernel<<<dim3((VOCAB + 127) / 128, ROWS / 128), 256>>>(pH3h, pH3l, pWh, pWl, out);
}

// round 6
// speedup vs baseline: 2.0514x; 1.7883x over previous
#include <cuda_runtime.h>
#include <cuda_bf16.h>
#include <math.h>
#include <cstdint>

// ---------------- problem constants ----------------
#define DIM    768
#define PE     200
#define KIN    1536
#define SPANL  20
#define NPAIR  256
#define ROWS   5120
#define EMB    128
#define VOCAB  30522
#define SEQ    512

// ---------------- scratch ----------------
__device__ __align__(16) float gX [NPAIR * KIN];
__device__ __align__(16) float gA [NPAIR * DIM];
__device__ __align__(16) float gP [SPANL * DIM];
__device__ __align__(16) float gH1[ROWS * DIM];
__device__ __align__(16) float gT [ROWS * DIM];
__device__ __align__(16) float gH2[ROWS * DIM];
__device__ __align__(16) float gH3[ROWS * EMB];
__device__ __align__(16) __nv_bfloat16 gH3h[ROWS * EMB];
__device__ __align__(16) __nv_bfloat16 gH3l[ROWS * EMB];
__device__ __align__(16) __nv_bfloat16 gWh [VOCAB * EMB];
__device__ __align__(16) __nv_bfloat16 gWl [VOCAB * EMB];

__device__ __forceinline__ float gelu_exact(float x) {
    return 0.5f * x * (1.0f + erff(x * 0.70710678118654752440f));
}

__device__ __forceinline__ uint32_t smem_u32(const void* p) {
    uint32_t a;
    asm("{ .reg .u64 t; cvta.to.shared.u64 t, %1; cvt.u32.u64 %0, t; }" : "=r"(a) : "l"(p));
    return a;
}

// ---------------- 1) gather span endpoints ----------------
__global__ void gather_kernel(const float* __restrict__ hs, const int* __restrict__ pairs) {
    int idx = blockIdx.x * 256 + threadIdx.x;
    if (idx >= NPAIR * KIN) return;
    int p = idx / KIN;
    int k = idx - p * KIN;
    int b = p >> 5;
    int tok, kk;
    if (k < DIM) { tok = pairs[2 * p];     kk = k; }
    else         { tok = pairs[2 * p + 1]; kk = k - DIM; }
    gX[idx] = hs[((size_t)(b * SEQ + tok)) * DIM + kk];
}

// ---------------- 2) positional projection ----------------
__global__ void pos_proj_kernel(const float* __restrict__ pe, const float* __restrict__ W1) {
    __shared__ float sp[PE];
    int l = blockIdx.y;
    int c = blockIdx.x * 256 + threadIdx.x;
    if (threadIdx.x < PE) sp[threadIdx.x] = pe[l * PE + threadIdx.x];
    __syncthreads();
    float acc = 0.0f;
    #pragma unroll 4
    for (int k = 0; k < PE; k++)
        acc += sp[k] * W1[(size_t)(KIN + k) * DIM + c];
    gP[l * DIM + c] = acc;
}

// ---------------- fp32 SGEMM ----------------
__global__ void sgemm_bias(const float* __restrict__ A, const float* __restrict__ B,
                           const float* __restrict__ bias, float* __restrict__ C,
                           int M, int N, int K) {
    __shared__ float As[16][68];
    __shared__ float Bs[16][68];
    int tid = threadIdx.x;
    int tx = tid & 15, ty = tid >> 4;
    int m0 = blockIdx.y * 64, n0 = blockIdx.x * 64;
    int ar = tid >> 2, aq = tid & 3;
    int bk = tid >> 4, bq = tid & 15;

    float acc[4][4];
    #pragma unroll
    for (int i = 0; i < 4; i++)
        #pragma unroll
        for (int j = 0; j < 4; j++) acc[i][j] = 0.0f;

    for (int k0 = 0; k0 < K; k0 += 16) {
        float4 av = *(const float4*)&A[(size_t)(m0 + ar) * K + k0 + aq * 4];
        float4 bv = *(const float4*)&B[(size_t)(k0 + bk) * N + n0 + bq * 4];
        As[aq * 4 + 0][ar] = av.x;
        As[aq * 4 + 1][ar] = av.y;
        As[aq * 4 + 2][ar] = av.z;
        As[aq * 4 + 3][ar] = av.w;
        *(float4*)&Bs[bk][bq * 4] = bv;
        __syncthreads();
        #pragma unroll
        for (int k = 0; k < 16; k++) {
            float4 a = *(const float4*)&As[k][ty * 4];
            float4 b = *(const float4*)&Bs[k][tx * 4];
            float ai[4] = {a.x, a.y, a.z, a.w};
            float bj[4] = {b.x, b.y, b.z, b.w};
            #pragma unroll
            for (int i = 0; i < 4; i++)
                #pragma unroll
                for (int j = 0; j < 4; j++) acc[i][j] += ai[i] * bj[j];
        }
        __syncthreads();
    }

    float bb[4] = {0.f, 0.f, 0.f, 0.f};
    if (bias) {
        #pragma unroll
        for (int j = 0; j < 4; j++) bb[j] = bias[n0 + tx * 4 + j];
    }
    #pragma unroll
    for (int i = 0; i < 4; i++) {
        int row = m0 + ty * 4 + i;
        #pragma unroll
        for (int j = 0; j < 4; j++)
            C[(size_t)row * N + n0 + tx * 4 + j] = acc[i][j] + bb[j];
    }
}

// ---------------- fused GELU + LayerNorm ----------------
__global__ void gelu_ln_kernel(const float* __restrict__ inA, const float* __restrict__ inP,
                               const float* __restrict__ gamma, const float* __restrict__ beta,
                               float* __restrict__ out, int addMode) {
    int row = blockIdx.x;
    int tid = threadIdx.x;
    float v[3];
    if (addMode) {
        const float* ra = inA + (size_t)(row / SPANL) * DIM;
        const float* rp = inP + (size_t)(row % SPANL) * DIM;
        #pragma unroll
        for (int c = 0; c < 3; c++) {
            int j = tid + c * 256;
            v[c] = gelu_exact(ra[j] + rp[j]);
        }
    } else {
        const float* ra = inA + (size_t)row * DIM;
        #pragma unroll
        for (int c = 0; c < 3; c++) {
            int j = tid + c * 256;
            v[c] = gelu_exact(ra[j]);
        }
    }
    float s  = v[0] + v[1] + v[2];
    float s2 = v[0] * v[0] + v[1] * v[1] + v[2] * v[2];
    #pragma unroll
    for (int o = 16; o > 0; o >>= 1) {
        s  += __shfl_xor_sync(0xffffffffu, s,  o);
        s2 += __shfl_xor_sync(0xffffffffu, s2, o);
    }
    __shared__ float rs[8], rs2[8];
    __shared__ float tmu, tinv;
    int wid = tid >> 5, lane = tid & 31;
    if (lane == 0) { rs[wid] = s; rs2[wid] = s2; }
    __syncthreads();
    if (tid == 0) {
        float a = 0.f, b = 0.f;
        #pragma unroll
        for (int i = 0; i < 8; i++) { a += rs[i]; b += rs2[i]; }
        float mu  = a * (1.0f / 768.0f);
        float var = b * (1.0f / 768.0f) - mu * mu;
        tmu = mu;
        tinv = rsqrtf(var + 1e-12f);
    }
    __syncthreads();
    float mu = tmu, inv = tinv;
    #pragma unroll
    for (int c = 0; c < 3; c++) {
        int j = tid + c * 256;
        out[(size_t)row * DIM + j] = (v[c] - mu) * inv * gamma[j] + beta[j];
    }
}

// ---------------- bf16 hi/lo split ----------------
__global__ void split_kernel(const float* __restrict__ src,
                             __nv_bfloat16* __restrict__ hi,
                             __nv_bfloat16* __restrict__ lo, int n) {
    int i = blockIdx.x * 256 + threadIdx.x;
    if (i >= n) return;
    float a = src[i];
    __nv_bfloat16 h = __float2bfloat16(a);
    float r = a - __bfloat162float(h);
    hi[i] = h;
    lo[i] = __float2bfloat16(r);
}

// ================= decoder v2: mma.sync + ldmatrix, K=128 smem-resident =================
// C[5120, 30522] = h3 @ Wdec^T, 3-term bf16 split (AhBh + AhBl + AlBh).
// CTA tile 128m x 64n, 8 warps (4m x 2n), warp tile 32m x 32n.
// smem: padded row stride 272B (16 x 17B16-chunks) -> conflict-free LDSM.

#define RSTR 272                     // bytes per tile row in smem
#define SZ_A (128 * RSTR)            // 34816 per split
#define SZ_B (64 * RSTR)             // 17408 per split
#define DEC_SMEM (2 * SZ_A + 2 * SZ_B)   // 104448

#define LDSM_X4(r0, r1, r2, r3, addr) \
    asm volatile("ldmatrix.sync.aligned.m8n8.x4.shared.b16 {%0,%1,%2,%3}, [%4];" \
                 : "=r"(r0), "=r"(r1), "=r"(r2), "=r"(r3) : "r"(addr))

__device__ __forceinline__ void mma_bf16(float* c, const uint32_t* a, uint32_t b0, uint32_t b1) {
    asm volatile(
        "mma.sync.aligned.m16n8k16.row.col.f32.bf16.bf16.f32 "
        "{%0,%1,%2,%3}, {%4,%5,%6,%7}, {%8,%9}, {%0,%1,%2,%3};\n"
        : "+f"(c[0]), "+f"(c[1]), "+f"(c[2]), "+f"(c[3])
        : "r"(a[0]), "r"(a[1]), "r"(a[2]), "r"(a[3]), "r"(b0), "r"(b1));
}

__global__ __launch_bounds__(256, 2)
void decoder_mma2(const __nv_bfloat16* __restrict__ Ah,
                  const __nv_bfloat16* __restrict__ Al,
                  const __nv_bfloat16* __restrict__ Bh,
                  const __nv_bfloat16* __restrict__ Bl,
                  float* __restrict__ C) {
    extern __shared__ char sm[];
    char* pAh = sm;
    char* pAl = sm + SZ_A;
    char* pBh = sm + 2 * SZ_A;
    char* pBl = sm + 2 * SZ_A + SZ_B;

    int tid = threadIdx.x;
    int warp = tid >> 5, lane = tid & 31;
    int m0 = blockIdx.y * 128, n0 = blockIdx.x * 64;

    // ---- load A tile (128 rows x 128 K), both splits ----
    #pragma unroll
    for (int it = 0; it < 8; it++) {
        int c = tid + it * 256;              // 2048 16B-chunks
        int r = c >> 4, p = c & 15;
        size_t off = (size_t)(m0 + r) * EMB + p * 8;
        *(uint4*)(pAh + r * RSTR + p * 16) = *(const uint4*)(Ah + off);
        *(uint4*)(pAl + r * RSTR + p * 16) = *(const uint4*)(Al + off);
    }
    // ---- load B tile (64 vocab rows x 128 K), both splits, guarded ----
    int nvalid = VOCAB - n0; if (nvalid > 64) nvalid = 64;
    #pragma unroll
    for (int it = 0; it < 4; it++) {
        int c = tid + it * 256;              // 1024 16B-chunks
        int r = c >> 4, p = c & 15;
        uint4 vh = make_uint4(0u, 0u, 0u, 0u), vl = vh;
        if (r < nvalid) {
            size_t off = (size_t)(n0 + r) * EMB + p * 8;
            vh = *(const uint4*)(Bh + off);
            vl = *(const uint4*)(Bl + off);
        }
        *(uint4*)(pBh + r * RSTR + p * 16) = vh;
        *(uint4*)(pBl + r * RSTR + p * 16) = vl;
    }
    __syncthreads();

    int wm = warp >> 1, wn = warp & 1;

    // ldmatrix lane addresses
    // A x4: lanes 0-7: m0-7@k0 | 8-15: m8-15@k0 | 16-23: m0-7@k8 | 24-31: m8-15@k8
    uint32_t aAddr = smem_u32(pAh) + (uint32_t)((wm * 32 + (lane & 15)) * RSTR + (lane >> 4) * 16);
    // B x4: lanes 0-7: n0-7@k0 | 8-15: n0-7@k8 | 16-23: n8-15@k0 | 24-31: n8-15@k8
    uint32_t bRow = wn * 32 + ((lane >> 4) << 3) + (lane & 7);
    uint32_t bAddr = smem_u32(pBh) + (uint32_t)(bRow * RSTR + ((lane >> 3) & 1) * 16);

    float acc[2][4][4];
    #pragma unroll
    for (int i = 0; i < 2; i++)
        #pragma unroll
        for (int j = 0; j < 4; j++)
            #pragma unroll
            for (int q = 0; q < 4; q++) acc[i][j][q] = 0.0f;

    #pragma unroll
    for (int s = 0; s < 8; s++) {
        uint32_t ah[2][4], al[2][4], bh[4][2], bl[4][2];
        #pragma unroll
        for (int mt = 0; mt < 2; mt++) {
            uint32_t ad = aAddr + mt * (16 * RSTR) + s * 32;
            LDSM_X4(ah[mt][0], ah[mt][1], ah[mt][2], ah[mt][3], ad);
            LDSM_X4(al[mt][0], al[mt][1], al[mt][2], al[mt][3], ad + SZ_A);
        }
        #pragma unroll
        for (int pr = 0; pr < 2; pr++) {
            uint32_t bd = bAddr + pr * (16 * RSTR) + s * 32;
            uint32_t r0, r1, r2, r3;
            LDSM_X4(r0, r1, r2, r3, bd);
            bh[pr * 2][0] = r0; bh[pr * 2][1] = r1;
            bh[pr * 2 + 1][0] = r2; bh[pr * 2 + 1][1] = r3;
            LDSM_X4(r0, r1, r2, r3, bd + SZ_B);
            bl[pr * 2][0] = r0; bl[pr * 2][1] = r1;
            bl[pr * 2 + 1][0] = r2; bl[pr * 2 + 1][1] = r3;
        }
        #pragma unroll
        for (int nt = 0; nt < 4; nt++)
            #pragma unroll
            for (int mt = 0; mt < 2; mt++) {
                mma_bf16(acc[mt][nt], ah[mt], bh[nt][0], bh[nt][1]);
                mma_bf16(acc[mt][nt], ah[mt], bl[nt][0], bl[nt][1]);
                mma_bf16(acc[mt][nt], al[mt], bh[nt][0], bh[nt][1]);
            }
    }

    // ---- epilogue ----
    int grp = lane >> 2, quad = lane & 3;
    #pragma unroll
    for (int mt = 0; mt < 2; mt++) {
        #pragma unroll
        for (int nt = 0; nt < 4; nt++) {
            int row = m0 + wm * 32 + mt * 16 + grp;
            int col = n0 + wn * 32 + nt * 8 + quad * 2;
            if (col < VOCAB) {   // VOCAB even, col even -> col+1 also valid
                *(float2*)&C[(size_t)row * VOCAB + col] =
                    make_float2(acc[mt][nt][0], acc[mt][nt][1]);
                *(float2*)&C[(size_t)(row + 8) * VOCAB + col] =
                    make_float2(acc[mt][nt][2], acc[mt][nt][3]);
            }
        }
    }
}

// ---------------- launcher ----------------
extern "C" void kernel_launch(void* const* d_in, const int* in_sizes, int n_in,
                              void* d_out, int out_size) {
    (void)in_sizes; (void)n_in; (void)out_size;
    const float* hs    = (const float*)d_in[0];
    const int*   pairs = (const int*)  d_in[1];
    const float* pos   = (const float*)d_in[2];
    const float* W1    = (const float*)d_in[3];
    const float* b1    = (const float*)d_in[4];
    const float* g1    = (const float*)d_in[5];
    const float* be1   = (const float*)d_in[6];
    const float* W2    = (const float*)d_in[7];
    const float* b2    = (const float*)d_in[8];
    const float* g2    = (const float*)d_in[9];
    const float* be2   = (const float*)d_in[10];
    const float* Wp    = (const float*)d_in[11];
    const float* bp    = (const float*)d_in[12];
    const float* Wdec  = (const float*)d_in[13];
    float* out = (float*)d_out;

    float *pX, *pA, *pP, *pH1, *pT, *pH2, *pH3;
    __nv_bfloat16 *pH3h, *pH3l, *pWh, *pWl;
    cudaGetSymbolAddress((void**)&pX,   gX);
    cudaGetSymbolAddress((void**)&pA,   gA);
    cudaGetSymbolAddress((void**)&pP,   gP);
    cudaGetSymbolAddress((void**)&pH1,  gH1);
    cudaGetSymbolAddress((void**)&pT,   gT);
    cudaGetSymbolAddress((void**)&pH2,  gH2);
    cudaGetSymbolAddress((void**)&pH3,  gH3);
    cudaGetSymbolAddress((void**)&pH3h, gH3h);
    cudaGetSymbolAddress((void**)&pH3l, gH3l);
    cudaGetSymbolAddress((void**)&pWh,  gWh);
    cudaGetSymbolAddress((void**)&pWl,  gWl);

    cudaFuncSetAttribute(decoder_mma2,
                         cudaFuncAttributeMaxDynamicSharedMemorySize, DEC_SMEM);

    // 1) gather endpoints
    gather_kernel<<<(NPAIR * KIN + 255) / 256, 256>>>(hs, pairs);
    // Wdec split early (no deps)
    split_kernel<<<(VOCAB * EMB + 255) / 256, 256>>>(Wdec, pWh, pWl, VOCAB * EMB);
    // 2) pair projection
    sgemm_bias<<<dim3(DIM / 64, NPAIR / 64), 256>>>(pX, W1, b1, pA, NPAIR, DIM, KIN);
    // 3) positional projection
    pos_proj_kernel<<<dim3(3, SPANL), 256>>>(pos, W1);
    // 4) h1 = LN(gelu(gA[pair] + gP[l]))
    gelu_ln_kernel<<<ROWS, 256>>>(pA, pP, g1, be1, pH1, 1);
    // 5) gT = h1 @ W2 + b2
    sgemm_bias<<<dim3(DIM / 64, ROWS / 64), 256>>>(pH1, W2, b2, pT, ROWS, DIM, DIM);
    // 6) h2 = LN(gelu(gT))
    gelu_ln_kernel<<<ROWS, 256>>>(pT, nullptr, g2, be2, pH2, 0);
    // 7) h3 = h2 @ Wp + bp
    sgemm_bias<<<dim3(EMB / 64, ROWS / 64), 256>>>(pH2, Wp, bp, pH3, ROWS, EMB, DIM);
    // 8) split h3, decoder on tensor cores (mma.sync + ldmatrix)
    split_kernel<<<(ROWS * EMB + 255) / 256, 256>>>(pH3, pH3h, pH3l, ROWS * EMB);
    decoder_mma2<<<dim3((VOCAB + 63) / 64, ROWS / 128), 256, DEC_SMEM>>>(pH3h, pH3l, pWh, pWl, out);
}